// round 9
// baseline (speedup 1.0000x reference)
#include <cuda_runtime.h>
#include <cuda_fp16.h>
#include <cuda_bf16.h>
#include <math.h>

// ---------------- problem constants ----------------
#define IN_DIM 256
#define HID 64
#define OUTD 16
#define NEG_SLOPE 0.01f

#define MAXN 50048
#define MAXE 1600000

// ---------------- device scratch (static, no allocs; zero-init at load) ----------------
__device__ __align__(16) __half g_Hw0h[(size_t)MAXN * HID]; // X @ W0 (fp16 for gather)
__device__ __align__(16) __half g_Hw1h[(size_t)MAXN * OUTD];// layer-1 features (fp16)
__device__ float g_pr0[MAXN], g_pc0[MAXN];
__device__ float g_pr1[MAXN], g_pc1[MAXN];
__device__ __align__(16) int g_cnt[MAXN];   // zero at load; scan re-zeroes each run
__device__ int   g_rowptr[MAXN + 1];
__device__ __align__(16) int g_pos[MAXE];
__device__ int   g_col[MAXE];

// ---------------- tf32 MMA helpers ----------------
__device__ __forceinline__ float f32_mask13(float x) {
    return __uint_as_float(__float_as_uint(x) & 0xFFFFE000u);
}
__device__ __forceinline__ void mma_tf32(float d[4], const float a[4], float b0, float b1) {
    asm volatile(
        "mma.sync.aligned.m16n8k8.row.col.f32.tf32.tf32.f32 "
        "{%0,%1,%2,%3}, {%4,%5,%6,%7}, {%8,%9}, {%0,%1,%2,%3};\n"
        : "+f"(d[0]), "+f"(d[1]), "+f"(d[2]), "+f"(d[3])
        : "r"(__float_as_uint(a[0])), "r"(__float_as_uint(a[1])),
          "r"(__float_as_uint(a[2])), "r"(__float_as_uint(a[3])),
          "r"(__float_as_uint(b0)), "r"(__float_as_uint(b1)));
}

// ---------------- FAT kernel: count_pos blocks + gemm0 blocks ----------------
#define GBM 128
#define EDGES_PER_BLK 1024

__global__ __launch_bounds__(128) void fat_kernel(
    const float* __restrict__ X, const float* __restrict__ W,
    const float* __restrict__ a0, const int* __restrict__ ei,
    int M, int E, int nCountBlks)
{
    __shared__ float As[GBM][36];
    __shared__ float Bs[32][64];
    __shared__ float Bl[32][64];

    int tid = threadIdx.x;

    if ((int)blockIdx.x < nCountBlks) {
        int base = blockIdx.x * EDGES_PER_BLK;
        #pragma unroll
        for (int h = 0; h < 2; h++) {
            int e = base + h * 512 + tid * 4;
            if (e + 3 < E) {
                int4 r = *(const int4*)(ei + e);
                int4 p;
                p.x = atomicAdd(&g_cnt[r.x], 1);
                p.y = atomicAdd(&g_cnt[r.y], 1);
                p.z = atomicAdd(&g_cnt[r.z], 1);
                p.w = atomicAdd(&g_cnt[r.w], 1);
                *(int4*)(g_pos + e) = p;
            } else {
                for (int j = e; j < E; j++) g_pos[j] = atomicAdd(&g_cnt[ei[j]], 1);
            }
        }
        return;
    }

    int lane = tid & 31, warp = tid >> 5;
    int gid = lane >> 2, tig = lane & 3;
    int block_m = (blockIdx.x - nCountBlks) * GBM;

    float d[2][8][4];
    #pragma unroll
    for (int mt = 0; mt < 2; mt++)
        #pragma unroll
        for (int nt = 0; nt < 8; nt++)
            #pragma unroll
            for (int q = 0; q < 4; q++) d[mt][nt][q] = 0.f;

    for (int k0 = 0; k0 < IN_DIM; k0 += 32) {
        #pragma unroll
        for (int i = 0; i < 8; i++) {
            int f = tid + 128 * i;
            int row = f >> 3, q = (f & 7) * 4;
            int gm = block_m + row;
            float4 v = (gm < M) ? *(const float4*)(X + (size_t)gm * IN_DIM + k0 + q)
                                : make_float4(0.f, 0.f, 0.f, 0.f);
            *(float4*)&As[row][q] = v;
        }
        #pragma unroll
        for (int i = 0; i < 4; i++) {
            int f = tid + 128 * i;
            int k = f >> 4, nq = (f & 15) * 4;
            float4 v = *(const float4*)(W + (size_t)(k0 + k) * HID + nq);
            float4 l;
            l.x = v.x - f32_mask13(v.x);
            l.y = v.y - f32_mask13(v.y);
            l.z = v.z - f32_mask13(v.z);
            l.w = v.w - f32_mask13(v.w);
            *(float4*)&Bs[k][nq] = v;
            *(float4*)&Bl[k][nq] = l;
        }
        __syncthreads();
        #pragma unroll
        for (int ks = 0; ks < 4; ks++) {
            float a[2][4], al[2][4];
            #pragma unroll
            for (int mt = 0; mt < 2; mt++) {
                int r = warp * 32 + mt * 16;
                a[mt][0] = As[r + gid][ks * 8 + tig];
                a[mt][1] = As[r + gid + 8][ks * 8 + tig];
                a[mt][2] = As[r + gid][ks * 8 + tig + 4];
                a[mt][3] = As[r + gid + 8][ks * 8 + tig + 4];
                #pragma unroll
                for (int q = 0; q < 4; q++) al[mt][q] = a[mt][q] - f32_mask13(a[mt][q]);
            }
            #pragma unroll
            for (int nt = 0; nt < 8; nt++) {
                float b0  = Bs[ks * 8 + tig][nt * 8 + gid];
                float b1  = Bs[ks * 8 + tig + 4][nt * 8 + gid];
                float bl0 = Bl[ks * 8 + tig][nt * 8 + gid];
                float bl1 = Bl[ks * 8 + tig + 4][nt * 8 + gid];
                #pragma unroll
                for (int mt = 0; mt < 2; mt++) {
                    mma_tf32(d[mt][nt], a[mt],  b0,  b1);   // hi*hi
                    mma_tf32(d[mt][nt], al[mt], b0,  b1);   // loA*hi
                    mma_tf32(d[mt][nt], a[mt],  bl0, bl1);  // hi*loB
                }
            }
        }
        __syncthreads();
    }

    float avv[8][2], aww[8][2];
    #pragma unroll
    for (int nt = 0; nt < 8; nt++) {
        avv[nt][0] = __ldg(a0 + nt * 8 + 2 * tig);
        avv[nt][1] = __ldg(a0 + nt * 8 + 2 * tig + 1);
        aww[nt][0] = __ldg(a0 + HID + nt * 8 + 2 * tig);
        aww[nt][1] = __ldg(a0 + HID + nt * 8 + 2 * tig + 1);
    }
    #pragma unroll
    for (int mt = 0; mt < 2; mt++) {
        int rloc = warp * 32 + mt * 16 + gid;
        int row0 = block_m + rloc;
        int row1 = row0 + 8;
        float prA = 0.f, pcA = 0.f, prB = 0.f, pcB = 0.f;
        #pragma unroll
        for (int nt = 0; nt < 8; nt++) {
            prA += d[mt][nt][0] * avv[nt][0] + d[mt][nt][1] * avv[nt][1];
            pcA += d[mt][nt][0] * aww[nt][0] + d[mt][nt][1] * aww[nt][1];
            prB += d[mt][nt][2] * avv[nt][0] + d[mt][nt][3] * avv[nt][1];
            pcB += d[mt][nt][2] * aww[nt][0] + d[mt][nt][3] * aww[nt][1];
            if (row0 < M)
                *(__half2*)(g_Hw0h + (size_t)row0 * HID + nt * 8 + 2 * tig) =
                    __floats2half2_rn(d[mt][nt][0], d[mt][nt][1]);
            if (row1 < M)
                *(__half2*)(g_Hw0h + (size_t)row1 * HID + nt * 8 + 2 * tig) =
                    __floats2half2_rn(d[mt][nt][2], d[mt][nt][3]);
        }
        #pragma unroll
        for (int o = 2; o; o >>= 1) {
            prA += __shfl_down_sync(0xffffffffu, prA, o, 4);
            pcA += __shfl_down_sync(0xffffffffu, pcA, o, 4);
            prB += __shfl_down_sync(0xffffffffu, prB, o, 4);
            pcB += __shfl_down_sync(0xffffffffu, pcB, o, 4);
        }
        if (tig == 0) {
            if (row0 < M) { g_pr0[row0] = prA; g_pc0[row0] = pcA; }
            if (row1 < M) { g_pr0[row1] = prB; g_pc0[row1] = pcB; }
        }
    }
}

// ---------------- scan: exclusive prefix over g_cnt -> g_rowptr; re-zeroes g_cnt ----------------
__global__ void scan_kernel(int n) {
    __shared__ int wsum[32];
    __shared__ int s_carry;
    int tid = threadIdx.x, lane = tid & 31, wid = tid >> 5;
    if (tid == 0) s_carry = 0;
    __syncthreads();
    int4* cnt4 = (int4*)g_cnt;
    int n4 = (n + 3) >> 2;
    for (int base = 0; base < n4; base += 1024) {
        int i = base + tid;
        int4 v = make_int4(0, 0, 0, 0);
        if (i < n4) {
            v = cnt4[i];
            cnt4[i] = make_int4(0, 0, 0, 0);
        }
        int s1 = v.x + v.y, s2 = s1 + v.z, s3 = s2 + v.w;
        int x = s3;
        #pragma unroll
        for (int o = 1; o < 32; o <<= 1) {
            int y = __shfl_up_sync(0xffffffffu, x, o);
            if (lane >= o) x += y;
        }
        if (lane == 31) wsum[wid] = x;
        __syncthreads();
        if (wid == 0) {
            int w = wsum[lane];
            #pragma unroll
            for (int o = 1; o < 32; o <<= 1) {
                int y = __shfl_up_sync(0xffffffffu, w, o);
                if (lane >= o) w += y;
            }
            wsum[lane] = w;
        }
        __syncthreads();
        int off = s_carry + (wid > 0 ? wsum[wid - 1] : 0) + (x - s3);
        if (i < n4) {
            int idx = i * 4;
            g_rowptr[idx]     = off;
            g_rowptr[idx + 1] = off + v.x;
            g_rowptr[idx + 2] = off + s1;
            g_rowptr[idx + 3] = off + s2;
        }
        __syncthreads();
        if (tid == 0) s_carry += wsum[31];
        __syncthreads();
    }
    if (tid == 0) g_rowptr[n] = s_carry;
}

// ---------------- atomic-free scatter (8 edges/thread for MLP) ----------------
__global__ void scatter_na_kernel(const int* __restrict__ ei, int E) {
    int t = blockIdx.x * blockDim.x + threadIdx.x;
    int e = t * 8;
    if (e + 7 < E) {
        int4 r0 = *(const int4*)(ei + e);
        int4 r1 = *(const int4*)(ei + e + 4);
        int4 p0 = *(const int4*)(g_pos + e);
        int4 p1 = *(const int4*)(g_pos + e + 4);
        int4 c0 = *(const int4*)(ei + E + e);
        int4 c1 = *(const int4*)(ei + E + e + 4);
        int b0 = g_rowptr[r0.x], b1 = g_rowptr[r0.y];
        int b2 = g_rowptr[r0.z], b3 = g_rowptr[r0.w];
        int b4 = g_rowptr[r1.x], b5 = g_rowptr[r1.y];
        int b6 = g_rowptr[r1.z], b7 = g_rowptr[r1.w];
        g_col[b0 + p0.x] = c0.x; g_col[b1 + p0.y] = c0.y;
        g_col[b2 + p0.z] = c0.z; g_col[b3 + p0.w] = c0.w;
        g_col[b4 + p1.x] = c1.x; g_col[b5 + p1.y] = c1.y;
        g_col[b6 + p1.z] = c1.z; g_col[b7 + p1.w] = c1.w;
    } else {
        for (int j = e; j < E; j++)
            g_col[g_rowptr[ei[j]] + g_pos[j]] = ei[E + j];
    }
}

// ---------------- layer-0: softmax+aggregate+ELU+GEMM1+pr1/pc1 fused, warp/row ----------------
// HFMA2 fp16 accumulation, flushed to fp32 every 4 steps (<=4 products/acc).
// W1 smem swizzle p(k,o) = (k&7)*160 + o*10 + (k>>3) -> conflict-free epilogue LDS.
__global__ __launch_bounds__(256) void agg64_kernel(
    const float* __restrict__ W1, const float* __restrict__ a1, int n)
{
    __shared__ float Ws[1280];
    __shared__ float a1s[2 * OUTD];
    int tid = threadIdx.x;
    #pragma unroll
    for (int i = 0; i < 4; i++) {
        int idx = tid + 256 * i;
        int k = idx >> 4, o = idx & 15;
        Ws[(k & 7) * 160 + o * 10 + (k >> 3)] = W1[idx];
    }
    if (tid < 2 * OUTD) a1s[tid] = a1[tid];
    __syncthreads();

    int w = (blockIdx.x * blockDim.x + tid) >> 5;
    int lane = tid & 31;
    if (w >= n) return;
    int s = g_rowptr[w], e = g_rowptr[w + 1];
    float prr = g_pr0[w];
    int sub = lane >> 3;    // edge slot within group of 4
    int dk  = lane & 7;     // 16-byte chunk of the 128-byte fp16 row
    const uint4* H4 = (const uint4*)g_Hw0h;
    float acc[8] = {0.f, 0.f, 0.f, 0.f, 0.f, 0.f, 0.f, 0.f};
    float denom = 0.f;
    const __half2 hz = __float2half2_rn(0.f);
    for (int base = s; base < e; base += 32) {
        int j = base + lane;
        float ev = 0.f; int c = 0;
        if (j < e) {
            c = g_col[j];
            float sc = prr + g_pc0[c];
            sc = (sc >= 0.f) ? sc : NEG_SLOPE * sc;
            ev = __expf(sc);
            denom += ev;
        }
        __half2 evh2 = __float2half2_rn(ev);
        unsigned evu = *(unsigned*)&evh2;
        int cnt = min(32, e - base);
        int ng = (cnt + 3) >> 2;
        __half2 h0 = hz, h1 = hz, h2 = hz, h3 = hz;
        for (int t = 0; t < ng; t++) {
            int idx = t * 4 + sub;
            unsigned eeu = __shfl_sync(0xffffffffu, evu, idx);  // 0 for invalid edges
            int      cc  = __shfl_sync(0xffffffffu, c, idx);
            __half2 ee2 = *(__half2*)&eeu;
            uint4 hv = H4[(size_t)cc * 8 + dk];
            h0 = __hfma2(*(__half2*)&hv.x, ee2, h0);
            h1 = __hfma2(*(__half2*)&hv.y, ee2, h1);
            h2 = __hfma2(*(__half2*)&hv.z, ee2, h2);
            h3 = __hfma2(*(__half2*)&hv.w, ee2, h3);
            if ((t & 3) == 3) {  // flush every 4 products
                float2 f;
                f = __half22float2(h0); acc[0] += f.x; acc[1] += f.y;
                f = __half22float2(h1); acc[2] += f.x; acc[3] += f.y;
                f = __half22float2(h2); acc[4] += f.x; acc[5] += f.y;
                f = __half22float2(h3); acc[6] += f.x; acc[7] += f.y;
                h0 = hz; h1 = hz; h2 = hz; h3 = hz;
            }
        }
        {   // final flush (zeros if already flushed — harmless)
            float2 f;
            f = __half22float2(h0); acc[0] += f.x; acc[1] += f.y;
            f = __half22float2(h1); acc[2] += f.x; acc[3] += f.y;
            f = __half22float2(h2); acc[4] += f.x; acc[5] += f.y;
            f = __half22float2(h3); acc[6] += f.x; acc[7] += f.y;
        }
    }
    #pragma unroll
    for (int o = 16; o; o >>= 1) denom += __shfl_xor_sync(0xffffffffu, denom, o);
    #pragma unroll
    for (int o = 8; o <= 16; o <<= 1)
        #pragma unroll
        for (int i = 0; i < 8; i++)
            acc[i] += __shfl_xor_sync(0xffffffffu, acc[i], o);
    float inv = (e > s) ? 1.0f / denom : 0.0f;
    float h8[8];
    #pragma unroll
    for (int i = 0; i < 8; i++) {
        float v = acc[i] * inv;
        h8[i] = (v > 0.f) ? v : expm1f(v);   // ELU
    }
    // fused GEMM1: lane (sub,dk) -> partial of outputs [sub*4, sub*4+4) over dims dk*8..+8
    float so[4] = {0.f, 0.f, 0.f, 0.f};
    #pragma unroll
    for (int i = 0; i < 8; i++) {
        const float* wp = Ws + i * 160 + dk;
        float hk = h8[i];
        #pragma unroll
        for (int q = 0; q < 4; q++)
            so[q] += hk * wp[(sub * 4 + q) * 10];   // conflict-free LDS
    }
    #pragma unroll
    for (int o = 4; o; o >>= 1)
        #pragma unroll
        for (int q = 0; q < 4; q++)
            so[q] += __shfl_xor_sync(0xffffffffu, so[q], o);
    float pr = so[0]*a1s[sub*4] + so[1]*a1s[sub*4+1] + so[2]*a1s[sub*4+2] + so[3]*a1s[sub*4+3];
    float pc = so[0]*a1s[OUTD+sub*4] + so[1]*a1s[OUTD+sub*4+1]
             + so[2]*a1s[OUTD+sub*4+2] + so[3]*a1s[OUTD+sub*4+3];
    pr += __shfl_xor_sync(0xffffffffu, pr, 8);
    pr += __shfl_xor_sync(0xffffffffu, pr, 16);
    pc += __shfl_xor_sync(0xffffffffu, pc, 8);
    pc += __shfl_xor_sync(0xffffffffu, pc, 16);
    if (dk == 0) {
        __half2 o0 = __floats2half2_rn(so[0], so[1]);
        __half2 o1 = __floats2half2_rn(so[2], so[3]);
        uint2 u;
        u.x = *(unsigned int*)&o0;
        u.y = *(unsigned int*)&o1;
        *(uint2*)(g_Hw1h + (size_t)w * OUTD + sub * 4) = u;
    }
    if (lane == 0) { g_pr1[w] = pr; g_pc1[w] = pc; }
}

// ---------------- layer-1 fused softmax+aggregate (D=16, fp16) + log_softmax ----------------
__global__ __launch_bounds__(256) void agg16_kernel(float* __restrict__ out, int n) {
    int w = (blockIdx.x * blockDim.x + threadIdx.x) >> 5;
    int lane = threadIdx.x & 31;
    if (w >= n) return;
    int s = g_rowptr[w], e = g_rowptr[w + 1];
    float prr = g_pr1[w];
    int sub = lane >> 1;     // edge within group of 16
    int dk  = lane & 1;      // which 16-byte half of the 32-byte fp16 row
    const uint4* H4 = (const uint4*)g_Hw1h;
    float acc[8] = {0.f, 0.f, 0.f, 0.f, 0.f, 0.f, 0.f, 0.f};
    float denom = 0.f;
    const __half2 hz = __float2half2_rn(0.f);
    for (int base = s; base < e; base += 32) {
        int j = base + lane;
        float ev = 0.f; int c = 0;
        if (j < e) {
            c = g_col[j];
            float sc = prr + g_pc1[c];
            sc = (sc >= 0.f) ? sc : NEG_SLOPE * sc;
            ev = __expf(sc);
            denom += ev;
        }
        __half2 evh2 = __float2half2_rn(ev);
        unsigned evu = *(unsigned*)&evh2;
        int cnt = min(32, e - base);
        int ng = (cnt + 15) >> 4;          // <=2 steps -> <=2 products per fp16 acc
        __half2 h0 = hz, h1 = hz, h2 = hz, h3 = hz;
        for (int t = 0; t < ng; t++) {
            int idx = t * 16 + sub;
            unsigned eeu = __shfl_sync(0xffffffffu, evu, idx);
            int      cc  = __shfl_sync(0xffffffffu, c, idx);
            __half2 ee2 = *(__half2*)&eeu;
            uint4 hv = H4[(size_t)cc * 2 + dk];
            h0 = __hfma2(*(__half2*)&hv.x, ee2, h0);
            h1 = __hfma2(*(__half2*)&hv.y, ee2, h1);
            h2 = __hfma2(*(__half2*)&hv.z, ee2, h2);
            h3 = __hfma2(*(__half2*)&hv.w, ee2, h3);
        }
        float2 f;
        f = __half22float2(h0); acc[0] += f.x; acc[1] += f.y;
        f = __half22float2(h1); acc[2] += f.x; acc[3] += f.y;
        f = __half22float2(h2); acc[4] += f.x; acc[5] += f.y;
        f = __half22float2(h3); acc[6] += f.x; acc[7] += f.y;
    }
    #pragma unroll
    for (int o = 16; o; o >>= 1) denom += __shfl_xor_sync(0xffffffffu, denom, o);
    #pragma unroll
    for (int o = 2; o <= 16; o <<= 1)
        #pragma unroll
        for (int i = 0; i < 8; i++)
            acc[i] += __shfl_xor_sync(0xffffffffu, acc[i], o);
    float inv = (e > s) ? 1.0f / denom : 0.0f;
    float v[8];
    #pragma unroll
    for (int i = 0; i < 8; i++) v[i] = acc[i] * inv;
    float m = v[0];
    #pragma unroll
    for (int i = 1; i < 8; i++) m = fmaxf(m, v[i]);
    m = fmaxf(m, __shfl_xor_sync(0xffffffffu, m, 1));
    float se = 0.f;
    #pragma unroll
    for (int i = 0; i < 8; i++) se += __expf(v[i] - m);
    se += __shfl_xor_sync(0xffffffffu, se, 1);
    float l = m + logf(se);
    if (lane < 2) {
        float* dst = out + (size_t)w * OUTD + dk * 8;
        *(float4*)(dst)     = make_float4(v[0] - l, v[1] - l, v[2] - l, v[3] - l);
        *(float4*)(dst + 4) = make_float4(v[4] - l, v[5] - l, v[6] - l, v[7] - l);
    }
}

// ---------------- launch ----------------
extern "C" void kernel_launch(void* const* d_in, const int* in_sizes, int n_in,
                              void* d_out, int out_size) {
    const float* X  = (const float*)d_in[0];
    const int*   ei = (const int*)  d_in[1];
    const float* W0 = (const float*)d_in[2];
    const float* a0 = (const float*)d_in[3];
    const float* W1 = (const float*)d_in[4];
    const float* a1 = (const float*)d_in[5];
    float* out = (float*)d_out;

    int N = in_sizes[0] / IN_DIM;
    int E = in_sizes[1] / 2;

    int nCountBlks = (E + EDGES_PER_BLK - 1) / EDGES_PER_BLK;
    int nGemmBlks  = (N + GBM - 1) / GBM;

    fat_kernel<<<nCountBlks + nGemmBlks, 128>>>(X, W0, a0, ei, N, E, nCountBlks);
    scan_kernel<<<1, 1024>>>(N);
    scatter_na_kernel<<<(E / 8 + 255) / 256, 256>>>(ei, E);

    // layer 0 aggregate + ELU + fused gemm1 + pr1/pc1
    agg64_kernel<<<(N + 7) / 8, 256>>>(W1, a1, N);

    // layer 1 aggregate + log-softmax
    agg16_kernel<<<(N + 7) / 8, 256>>>(out, N);
}

// round 10
// speedup vs baseline: 1.0579x; 1.0579x over previous
#include <cuda_runtime.h>
#include <cuda_fp16.h>
#include <cuda_bf16.h>
#include <math.h>

// ---------------- problem constants ----------------
#define IN_DIM 256
#define HID 64
#define OUTD 16
#define NEG_SLOPE 0.01f

#define MAXN 50048
#define MAXE 1600000

// ---------------- device scratch (static, no allocs; zero-init at load) ----------------
__device__ __align__(16) __half g_Hw0h[(size_t)MAXN * HID]; // X @ W0 (fp16 for gather)
__device__ __align__(16) __half g_Hw1h[(size_t)MAXN * OUTD];// layer-1 features (fp16)
__device__ float g_pr0[MAXN], g_pc0[MAXN];
__device__ float g_pr1[MAXN], g_pc1[MAXN];
__device__ __align__(16) int g_cnt[MAXN];   // zero at load; scan re-zeroes each run
__device__ int   g_rowptr[MAXN + 1];
__device__ __align__(16) int g_pos[MAXE];
__device__ int   g_col[MAXE];

// ---------------- native fp16 HMMA m16n8k16, fp32 accumulate ----------------
__device__ __forceinline__ void mma_f16(float d[4], const unsigned a[4],
                                        unsigned b0, unsigned b1) {
    asm volatile(
        "mma.sync.aligned.m16n8k16.row.col.f32.f16.f16.f32 "
        "{%0,%1,%2,%3}, {%4,%5,%6,%7}, {%8,%9}, {%0,%1,%2,%3};\n"
        : "+f"(d[0]), "+f"(d[1]), "+f"(d[2]), "+f"(d[3])
        : "r"(a[0]), "r"(a[1]), "r"(a[2]), "r"(a[3]), "r"(b0), "r"(b1));
}

// ---------------- FAT kernel: count_pos blocks + gemm0 blocks ----------------
// GEMM via split-precision fp16 HMMA: x = hi + lo (hi = rn16(x));
// D = Ah*Bh + Al*Bh + Ah*Bl  (fp32 accum; dropped Al*Bl ~ 2^-22)
#define GBM 128
#define EDGES_PER_BLK 1024
#define ASTRIDE 40   // halves; banks (20*gid + tig) mod 32 -> conflict-free frags

__global__ __launch_bounds__(128) void fat_kernel(
    const float* __restrict__ X, const float* __restrict__ W,
    const float* __restrict__ a0, const int* __restrict__ ei,
    int M, int E, int nCountBlks)
{
    __shared__ __half Ah[GBM][ASTRIDE];   // 10KB
    __shared__ __half Al[GBM][ASTRIDE];   // 10KB
    __shared__ __half Bh[64][ASTRIDE];    // 5KB  (n-major: [n][k])
    __shared__ __half Bl[64][ASTRIDE];    // 5KB

    int tid = threadIdx.x;

    if ((int)blockIdx.x < nCountBlks) {
        int base = blockIdx.x * EDGES_PER_BLK;
        #pragma unroll
        for (int h = 0; h < 2; h++) {
            int e = base + h * 512 + tid * 4;
            if (e + 3 < E) {
                int4 r = *(const int4*)(ei + e);
                int4 p;
                p.x = atomicAdd(&g_cnt[r.x], 1);
                p.y = atomicAdd(&g_cnt[r.y], 1);
                p.z = atomicAdd(&g_cnt[r.z], 1);
                p.w = atomicAdd(&g_cnt[r.w], 1);
                *(int4*)(g_pos + e) = p;
            } else {
                for (int j = e; j < E; j++) g_pos[j] = atomicAdd(&g_cnt[ei[j]], 1);
            }
        }
        return;
    }

    int lane = tid & 31, warp = tid >> 5;
    int gid = lane >> 2, tig = lane & 3;
    int block_m = (blockIdx.x - nCountBlks) * GBM;

    float d[2][8][4];
    #pragma unroll
    for (int mt = 0; mt < 2; mt++)
        #pragma unroll
        for (int nt = 0; nt < 8; nt++)
            #pragma unroll
            for (int q = 0; q < 4; q++) d[mt][nt][q] = 0.f;

    for (int k0 = 0; k0 < IN_DIM; k0 += 32) {
        // stage A: 128 rows x 32 k, split into hi/lo fp16
        #pragma unroll
        for (int i = 0; i < 8; i++) {
            int f = tid + 128 * i;            // 0..1023 float4 slots
            int row = f >> 3, kq = (f & 7) * 4;
            int gm = block_m + row;
            float4 v = (gm < M) ? *(const float4*)(X + (size_t)gm * IN_DIM + k0 + kq)
                                : make_float4(0.f, 0.f, 0.f, 0.f);
            __half hx = __float2half_rn(v.x), hy = __float2half_rn(v.y);
            __half hz = __float2half_rn(v.z), hw = __float2half_rn(v.w);
            *(__half2*)&Ah[row][kq]     = __halves2half2(hx, hy);
            *(__half2*)&Ah[row][kq + 2] = __halves2half2(hz, hw);
            *(__half2*)&Al[row][kq]     = __floats2half2_rn(v.x - __half2float(hx),
                                                            v.y - __half2float(hy));
            *(__half2*)&Al[row][kq + 2] = __floats2half2_rn(v.z - __half2float(hz),
                                                            v.w - __half2float(hw));
        }
        // stage B: 32 k x 64 n, transposed to [n][k], hi/lo fp16
        #pragma unroll
        for (int i = 0; i < 4; i++) {
            int f = tid + 128 * i;            // 0..511 float4 slots
            int k = f >> 4, nq = (f & 15) * 4;
            float4 v = *(const float4*)(W + (size_t)(k0 + k) * HID + nq);
            __half hx = __float2half_rn(v.x), hy = __float2half_rn(v.y);
            __half hz = __float2half_rn(v.z), hw = __float2half_rn(v.w);
            Bh[nq + 0][k] = hx; Bh[nq + 1][k] = hy;
            Bh[nq + 2][k] = hz; Bh[nq + 3][k] = hw;
            Bl[nq + 0][k] = __float2half_rn(v.x - __half2float(hx));
            Bl[nq + 1][k] = __float2half_rn(v.y - __half2float(hy));
            Bl[nq + 2][k] = __float2half_rn(v.z - __half2float(hz));
            Bl[nq + 3][k] = __float2half_rn(v.w - __half2float(hw));
        }
        __syncthreads();
        #pragma unroll
        for (int ks = 0; ks < 2; ks++) {     // two k16 steps per 32-k chunk
            int kb = ks * 16;
            unsigned ah[2][4], al[2][4];
            #pragma unroll
            for (int mt = 0; mt < 2; mt++) {
                int r = warp * 32 + mt * 16 + gid;
                ah[mt][0] = *(unsigned*)&Ah[r][kb + 2 * tig];
                ah[mt][1] = *(unsigned*)&Ah[r + 8][kb + 2 * tig];
                ah[mt][2] = *(unsigned*)&Ah[r][kb + 2 * tig + 8];
                ah[mt][3] = *(unsigned*)&Ah[r + 8][kb + 2 * tig + 8];
                al[mt][0] = *(unsigned*)&Al[r][kb + 2 * tig];
                al[mt][1] = *(unsigned*)&Al[r + 8][kb + 2 * tig];
                al[mt][2] = *(unsigned*)&Al[r][kb + 2 * tig + 8];
                al[mt][3] = *(unsigned*)&Al[r + 8][kb + 2 * tig + 8];
            }
            #pragma unroll
            for (int nt = 0; nt < 8; nt++) {
                int nrow = nt * 8 + gid;
                unsigned bh0 = *(unsigned*)&Bh[nrow][kb + 2 * tig];
                unsigned bh1 = *(unsigned*)&Bh[nrow][kb + 2 * tig + 8];
                unsigned bl0 = *(unsigned*)&Bl[nrow][kb + 2 * tig];
                unsigned bl1 = *(unsigned*)&Bl[nrow][kb + 2 * tig + 8];
                #pragma unroll
                for (int mt = 0; mt < 2; mt++) {
                    mma_f16(d[mt][nt], ah[mt], bh0, bh1);   // hi*hi
                    mma_f16(d[mt][nt], al[mt], bh0, bh1);   // loA*hi
                    mma_f16(d[mt][nt], ah[mt], bl0, bl1);   // hi*loB
                }
            }
        }
        __syncthreads();
    }

    // epilogue: store Hw0 (fp16) + fused pr0/pc0 (fp32) — layout same as before
    float avv[8][2], aww[8][2];
    #pragma unroll
    for (int nt = 0; nt < 8; nt++) {
        avv[nt][0] = __ldg(a0 + nt * 8 + 2 * tig);
        avv[nt][1] = __ldg(a0 + nt * 8 + 2 * tig + 1);
        aww[nt][0] = __ldg(a0 + HID + nt * 8 + 2 * tig);
        aww[nt][1] = __ldg(a0 + HID + nt * 8 + 2 * tig + 1);
    }
    #pragma unroll
    for (int mt = 0; mt < 2; mt++) {
        int rloc = warp * 32 + mt * 16 + gid;
        int row0 = block_m + rloc;
        int row1 = row0 + 8;
        float prA = 0.f, pcA = 0.f, prB = 0.f, pcB = 0.f;
        #pragma unroll
        for (int nt = 0; nt < 8; nt++) {
            prA += d[mt][nt][0] * avv[nt][0] + d[mt][nt][1] * avv[nt][1];
            pcA += d[mt][nt][0] * aww[nt][0] + d[mt][nt][1] * aww[nt][1];
            prB += d[mt][nt][2] * avv[nt][0] + d[mt][nt][3] * avv[nt][1];
            pcB += d[mt][nt][2] * aww[nt][0] + d[mt][nt][3] * aww[nt][1];
            if (row0 < M)
                *(__half2*)(g_Hw0h + (size_t)row0 * HID + nt * 8 + 2 * tig) =
                    __floats2half2_rn(d[mt][nt][0], d[mt][nt][1]);
            if (row1 < M)
                *(__half2*)(g_Hw0h + (size_t)row1 * HID + nt * 8 + 2 * tig) =
                    __floats2half2_rn(d[mt][nt][2], d[mt][nt][3]);
        }
        #pragma unroll
        for (int o = 2; o; o >>= 1) {
            prA += __shfl_down_sync(0xffffffffu, prA, o, 4);
            pcA += __shfl_down_sync(0xffffffffu, pcA, o, 4);
            prB += __shfl_down_sync(0xffffffffu, prB, o, 4);
            pcB += __shfl_down_sync(0xffffffffu, pcB, o, 4);
        }
        if (tig == 0) {
            if (row0 < M) { g_pr0[row0] = prA; g_pc0[row0] = pcA; }
            if (row1 < M) { g_pr0[row1] = prB; g_pc0[row1] = pcB; }
        }
    }
}

// ---------------- scan: exclusive prefix over g_cnt -> g_rowptr; re-zeroes g_cnt ----------------
__global__ void scan_kernel(int n) {
    __shared__ int wsum[32];
    __shared__ int s_carry;
    int tid = threadIdx.x, lane = tid & 31, wid = tid >> 5;
    if (tid == 0) s_carry = 0;
    __syncthreads();
    int4* cnt4 = (int4*)g_cnt;
    int n4 = (n + 3) >> 2;
    for (int base = 0; base < n4; base += 1024) {
        int i = base + tid;
        int4 v = make_int4(0, 0, 0, 0);
        if (i < n4) {
            v = cnt4[i];
            cnt4[i] = make_int4(0, 0, 0, 0);
        }
        int s1 = v.x + v.y, s2 = s1 + v.z, s3 = s2 + v.w;
        int x = s3;
        #pragma unroll
        for (int o = 1; o < 32; o <<= 1) {
            int y = __shfl_up_sync(0xffffffffu, x, o);
            if (lane >= o) x += y;
        }
        if (lane == 31) wsum[wid] = x;
        __syncthreads();
        if (wid == 0) {
            int w = wsum[lane];
            #pragma unroll
            for (int o = 1; o < 32; o <<= 1) {
                int y = __shfl_up_sync(0xffffffffu, w, o);
                if (lane >= o) w += y;
            }
            wsum[lane] = w;
        }
        __syncthreads();
        int off = s_carry + (wid > 0 ? wsum[wid - 1] : 0) + (x - s3);
        if (i < n4) {
            int idx = i * 4;
            g_rowptr[idx]     = off;
            g_rowptr[idx + 1] = off + v.x;
            g_rowptr[idx + 2] = off + s1;
            g_rowptr[idx + 3] = off + s2;
        }
        __syncthreads();
        if (tid == 0) s_carry += wsum[31];
        __syncthreads();
    }
    if (tid == 0) g_rowptr[n] = s_carry;
}

// ---------------- atomic-free scatter (8 edges/thread) ----------------
__global__ void scatter_na_kernel(const int* __restrict__ ei, int E) {
    int t = blockIdx.x * blockDim.x + threadIdx.x;
    int e = t * 8;
    if (e + 7 < E) {
        int4 r0 = *(const int4*)(ei + e);
        int4 r1 = *(const int4*)(ei + e + 4);
        int4 p0 = *(const int4*)(g_pos + e);
        int4 p1 = *(const int4*)(g_pos + e + 4);
        int4 c0 = *(const int4*)(ei + E + e);
        int4 c1 = *(const int4*)(ei + E + e + 4);
        int b0 = g_rowptr[r0.x], b1 = g_rowptr[r0.y];
        int b2 = g_rowptr[r0.z], b3 = g_rowptr[r0.w];
        int b4 = g_rowptr[r1.x], b5 = g_rowptr[r1.y];
        int b6 = g_rowptr[r1.z], b7 = g_rowptr[r1.w];
        g_col[b0 + p0.x] = c0.x; g_col[b1 + p0.y] = c0.y;
        g_col[b2 + p0.z] = c0.z; g_col[b3 + p0.w] = c0.w;
        g_col[b4 + p1.x] = c1.x; g_col[b5 + p1.y] = c1.y;
        g_col[b6 + p1.z] = c1.z; g_col[b7 + p1.w] = c1.w;
    } else {
        for (int j = e; j < E; j++)
            g_col[g_rowptr[ei[j]] + g_pos[j]] = ei[E + j];
    }
}

// ---------------- layer-0: softmax+aggregate+ELU+GEMM1+pr1/pc1 fused, warp/row ----------------
__global__ __launch_bounds__(256) void agg64_kernel(
    const float* __restrict__ W1, const float* __restrict__ a1, int n)
{
    __shared__ float Ws[1280];
    __shared__ float a1s[2 * OUTD];
    int tid = threadIdx.x;
    #pragma unroll
    for (int i = 0; i < 4; i++) {
        int idx = tid + 256 * i;
        int k = idx >> 4, o = idx & 15;
        Ws[(k & 7) * 160 + o * 10 + (k >> 3)] = W1[idx];
    }
    if (tid < 2 * OUTD) a1s[tid] = a1[tid];
    __syncthreads();

    int w = (blockIdx.x * blockDim.x + tid) >> 5;
    int lane = tid & 31;
    if (w >= n) return;
    int s = g_rowptr[w], e = g_rowptr[w + 1];
    float prr = g_pr0[w];
    int sub = lane >> 3;
    int dk  = lane & 7;
    const uint4* H4 = (const uint4*)g_Hw0h;
    float acc[8] = {0.f, 0.f, 0.f, 0.f, 0.f, 0.f, 0.f, 0.f};
    float denom = 0.f;
    const __half2 hz = __float2half2_rn(0.f);
    for (int base = s; base < e; base += 32) {
        int j = base + lane;
        float ev = 0.f; int c = 0;
        if (j < e) {
            c = g_col[j];
            float sc = prr + g_pc0[c];
            sc = (sc >= 0.f) ? sc : NEG_SLOPE * sc;
            ev = __expf(sc);
            denom += ev;
        }
        __half2 evh2 = __float2half2_rn(ev);
        unsigned evu = *(unsigned*)&evh2;
        int cnt = min(32, e - base);
        int ng = (cnt + 3) >> 2;
        __half2 h0 = hz, h1 = hz, h2 = hz, h3 = hz;
        for (int t = 0; t < ng; t++) {
            int idx = t * 4 + sub;
            unsigned eeu = __shfl_sync(0xffffffffu, evu, idx);
            int      cc  = __shfl_sync(0xffffffffu, c, idx);
            __half2 ee2 = *(__half2*)&eeu;
            uint4 hv = H4[(size_t)cc * 8 + dk];
            h0 = __hfma2(*(__half2*)&hv.x, ee2, h0);
            h1 = __hfma2(*(__half2*)&hv.y, ee2, h1);
            h2 = __hfma2(*(__half2*)&hv.z, ee2, h2);
            h3 = __hfma2(*(__half2*)&hv.w, ee2, h3);
            if ((t & 3) == 3) {
                float2 f;
                f = __half22float2(h0); acc[0] += f.x; acc[1] += f.y;
                f = __half22float2(h1); acc[2] += f.x; acc[3] += f.y;
                f = __half22float2(h2); acc[4] += f.x; acc[5] += f.y;
                f = __half22float2(h3); acc[6] += f.x; acc[7] += f.y;
                h0 = hz; h1 = hz; h2 = hz; h3 = hz;
            }
        }
        {
            float2 f;
            f = __half22float2(h0); acc[0] += f.x; acc[1] += f.y;
            f = __half22float2(h1); acc[2] += f.x; acc[3] += f.y;
            f = __half22float2(h2); acc[4] += f.x; acc[5] += f.y;
            f = __half22float2(h3); acc[6] += f.x; acc[7] += f.y;
        }
    }
    #pragma unroll
    for (int o = 16; o; o >>= 1) denom += __shfl_xor_sync(0xffffffffu, denom, o);
    #pragma unroll
    for (int o = 8; o <= 16; o <<= 1)
        #pragma unroll
        for (int i = 0; i < 8; i++)
            acc[i] += __shfl_xor_sync(0xffffffffu, acc[i], o);
    float inv = (e > s) ? 1.0f / denom : 0.0f;
    float h8[8];
    #pragma unroll
    for (int i = 0; i < 8; i++) {
        float v = acc[i] * inv;
        h8[i] = (v > 0.f) ? v : expm1f(v);   // ELU
    }
    float so[4] = {0.f, 0.f, 0.f, 0.f};
    #pragma unroll
    for (int i = 0; i < 8; i++) {
        const float* wp = Ws + i * 160 + dk;
        float hk = h8[i];
        #pragma unroll
        for (int q = 0; q < 4; q++)
            so[q] += hk * wp[(sub * 4 + q) * 10];
    }
    #pragma unroll
    for (int o = 4; o; o >>= 1)
        #pragma unroll
        for (int q = 0; q < 4; q++)
            so[q] += __shfl_xor_sync(0xffffffffu, so[q], o);
    float pr = so[0]*a1s[sub*4] + so[1]*a1s[sub*4+1] + so[2]*a1s[sub*4+2] + so[3]*a1s[sub*4+3];
    float pc = so[0]*a1s[OUTD+sub*4] + so[1]*a1s[OUTD+sub*4+1]
             + so[2]*a1s[OUTD+sub*4+2] + so[3]*a1s[OUTD+sub*4+3];
    pr += __shfl_xor_sync(0xffffffffu, pr, 8);
    pr += __shfl_xor_sync(0xffffffffu, pr, 16);
    pc += __shfl_xor_sync(0xffffffffu, pc, 8);
    pc += __shfl_xor_sync(0xffffffffu, pc, 16);
    if (dk == 0) {
        __half2 o0 = __floats2half2_rn(so[0], so[1]);
        __half2 o1 = __floats2half2_rn(so[2], so[3]);
        uint2 u;
        u.x = *(unsigned int*)&o0;
        u.y = *(unsigned int*)&o1;
        *(uint2*)(g_Hw1h + (size_t)w * OUTD + sub * 4) = u;
    }
    if (lane == 0) { g_pr1[w] = pr; g_pc1[w] = pc; }
}

// ---------------- layer-1 fused softmax+aggregate (D=16, fp16) + log_softmax ----------------
__global__ __launch_bounds__(256) void agg16_kernel(float* __restrict__ out, int n) {
    int w = (blockIdx.x * blockDim.x + threadIdx.x) >> 5;
    int lane = threadIdx.x & 31;
    if (w >= n) return;
    int s = g_rowptr[w], e = g_rowptr[w + 1];
    float prr = g_pr1[w];
    int sub = lane >> 1;
    int dk  = lane & 1;
    const uint4* H4 = (const uint4*)g_Hw1h;
    float acc[8] = {0.f, 0.f, 0.f, 0.f, 0.f, 0.f, 0.f, 0.f};
    float denom = 0.f;
    const __half2 hz = __float2half2_rn(0.f);
    for (int base = s; base < e; base += 32) {
        int j = base + lane;
        float ev = 0.f; int c = 0;
        if (j < e) {
            c = g_col[j];
            float sc = prr + g_pc1[c];
            sc = (sc >= 0.f) ? sc : NEG_SLOPE * sc;
            ev = __expf(sc);
            denom += ev;
        }
        __half2 evh2 = __float2half2_rn(ev);
        unsigned evu = *(unsigned*)&evh2;
        int cnt = min(32, e - base);
        int ng = (cnt + 15) >> 4;
        __half2 h0 = hz, h1 = hz, h2 = hz, h3 = hz;
        for (int t = 0; t < ng; t++) {
            int idx = t * 16 + sub;
            unsigned eeu = __shfl_sync(0xffffffffu, evu, idx);
            int      cc  = __shfl_sync(0xffffffffu, c, idx);
            __half2 ee2 = *(__half2*)&eeu;
            uint4 hv = H4[(size_t)cc * 2 + dk];
            h0 = __hfma2(*(__half2*)&hv.x, ee2, h0);
            h1 = __hfma2(*(__half2*)&hv.y, ee2, h1);
            h2 = __hfma2(*(__half2*)&hv.z, ee2, h2);
            h3 = __hfma2(*(__half2*)&hv.w, ee2, h3);
        }
        float2 f;
        f = __half22float2(h0); acc[0] += f.x; acc[1] += f.y;
        f = __half22float2(h1); acc[2] += f.x; acc[3] += f.y;
        f = __half22float2(h2); acc[4] += f.x; acc[5] += f.y;
        f = __half22float2(h3); acc[6] += f.x; acc[7] += f.y;
    }
    #pragma unroll
    for (int o = 16; o; o >>= 1) denom += __shfl_xor_sync(0xffffffffu, denom, o);
    #pragma unroll
    for (int o = 2; o <= 16; o <<= 1)
        #pragma unroll
        for (int i = 0; i < 8; i++)
            acc[i] += __shfl_xor_sync(0xffffffffu, acc[i], o);
    float inv = (e > s) ? 1.0f / denom : 0.0f;
    float v[8];
    #pragma unroll
    for (int i = 0; i < 8; i++) v[i] = acc[i] * inv;
    float m = v[0];
    #pragma unroll
    for (int i = 1; i < 8; i++) m = fmaxf(m, v[i]);
    m = fmaxf(m, __shfl_xor_sync(0xffffffffu, m, 1));
    float se = 0.f;
    #pragma unroll
    for (int i = 0; i < 8; i++) se += __expf(v[i] - m);
    se += __shfl_xor_sync(0xffffffffu, se, 1);
    float l = m + logf(se);
    if (lane < 2) {
        float* dst = out + (size_t)w * OUTD + dk * 8;
        *(float4*)(dst)     = make_float4(v[0] - l, v[1] - l, v[2] - l, v[3] - l);
        *(float4*)(dst + 4) = make_float4(v[4] - l, v[5] - l, v[6] - l, v[7] - l);
    }
}

// ---------------- launch ----------------
extern "C" void kernel_launch(void* const* d_in, const int* in_sizes, int n_in,
                              void* d_out, int out_size) {
    const float* X  = (const float*)d_in[0];
    const int*   ei = (const int*)  d_in[1];
    const float* W0 = (const float*)d_in[2];
    const float* a0 = (const float*)d_in[3];
    const float* W1 = (const float*)d_in[4];
    const float* a1 = (const float*)d_in[5];
    float* out = (float*)d_out;

    int N = in_sizes[0] / IN_DIM;
    int E = in_sizes[1] / 2;

    int nCountBlks = (E + EDGES_PER_BLK - 1) / EDGES_PER_BLK;
    int nGemmBlks  = (N + GBM - 1) / GBM;

    fat_kernel<<<nCountBlks + nGemmBlks, 128>>>(X, W0, a0, ei, N, E, nCountBlks);
    scan_kernel<<<1, 1024>>>(N);
    scatter_na_kernel<<<(E / 8 + 255) / 256, 256>>>(ei, E);

    // layer 0 aggregate + ELU + fused gemm1 + pr1/pc1
    agg64_kernel<<<(N + 7) / 8, 256>>>(W1, a1, N);

    // layer 1 aggregate + log-softmax
    agg16_kernel<<<(N + 7) / 8, 256>>>(out, N);
}